// round 2
// baseline (speedup 1.0000x reference)
#include <cuda_runtime.h>

#define BSZ 4
#define SEQ 2048
#define EMB 1024
#define NH  16
#define HD  64
#define MTOT (BSZ*SEQ)       /* 8192 */
#define NQKV (3*EMB)         /* 3072 */
#define NEG_BIG (-3.0e38f)

// Scratch (device globals: allocation-free per harness rules)
__device__ float g_q[(size_t)BSZ*NH*SEQ*HD];   // [B,H,S,D]
__device__ float g_k[(size_t)BSZ*NH*SEQ*HD];
__device__ float g_v[(size_t)BSZ*NH*SEQ*HD];
__device__ float g_y[(size_t)MTOT*EMB];        // attention output, [B*S, E]

// ---------------------------------------------------------------------------
// QKV GEMM: x[8192,1024] @ w_qkv[1024,3072] + b, scatter into g_q/g_k/g_v
// 128x128 tile, BK=8, 256 threads, 8x8 per-thread (split 4+4 cols/rows)
// ---------------------------------------------------------------------------
__global__ __launch_bounds__(256) void qkv_gemm_kernel(
    const float* __restrict__ A, const float* __restrict__ W,
    const float* __restrict__ bias)
{
    __shared__ float As[8][132];   // transposed A tile, padded
    __shared__ float Bs[8][128];
    const int tid = threadIdx.x;
    const int tx = tid & 15, ty = tid >> 4;
    const int bm = blockIdx.y * 128, bn = blockIdx.x * 128;

    float acc[8][8];
#pragma unroll
    for (int i = 0; i < 8; i++)
#pragma unroll
        for (int j = 0; j < 8; j++) acc[i][j] = 0.f;

    const int ar = tid >> 1, ac = (tid & 1) << 2;
    const int br = tid >> 5, bc = (tid & 31) << 2;
    const float* Ap = A + (size_t)(bm + ar) * EMB + ac;
    const float* Wp = W + (size_t)br * NQKV + bn + bc;

    for (int k0 = 0; k0 < EMB; k0 += 8) {
        float4 av = *(const float4*)(Ap + k0);
        As[ac+0][ar] = av.x; As[ac+1][ar] = av.y;
        As[ac+2][ar] = av.z; As[ac+3][ar] = av.w;
        *(float4*)&Bs[br][bc] = *(const float4*)(Wp + (size_t)k0 * NQKV);
        __syncthreads();
#pragma unroll
        for (int k = 0; k < 8; k++) {
            float a[8], b[8];
            float4 t;
            t = *(const float4*)&As[k][ty*4];      a[0]=t.x; a[1]=t.y; a[2]=t.z; a[3]=t.w;
            t = *(const float4*)&As[k][64+ty*4];   a[4]=t.x; a[5]=t.y; a[6]=t.z; a[7]=t.w;
            t = *(const float4*)&Bs[k][tx*4];      b[0]=t.x; b[1]=t.y; b[2]=t.z; b[3]=t.w;
            t = *(const float4*)&Bs[k][64+tx*4];   b[4]=t.x; b[5]=t.y; b[6]=t.z; b[7]=t.w;
#pragma unroll
            for (int i = 0; i < 8; i++)
#pragma unroll
                for (int j = 0; j < 8; j++)
                    acc[i][j] = fmaf(a[i], b[j], acc[i][j]);
        }
        __syncthreads();
    }

    // Epilogue: bias + scatter to [B,H,S,D]. 128-col tiles never straddle a
    // q/k/v section (3072/128=24, sections at multiples of 1024) and 4-col
    // quads never straddle a head (D=64), so float4 stores are legal.
#pragma unroll
    for (int ih = 0; ih < 2; ih++)
#pragma unroll
        for (int i = 0; i < 4; i++) {
            const int m = bm + ih*64 + ty*4 + i;
            const int bb = m >> 11;          // / SEQ
            const int s  = m & (SEQ-1);
#pragma unroll
            for (int jh = 0; jh < 2; jh++) {
                const int n0 = bn + jh*64 + tx*4;
                const int sect = n0 >> 10;
                const int e = n0 & (EMB-1);
                const int h = e >> 6, d = e & 63;
                float* dst = (sect == 0) ? g_q : (sect == 1) ? g_k : g_v;
                float4 v;
                v.x = acc[ih*4+i][jh*4+0] + bias[n0+0];
                v.y = acc[ih*4+i][jh*4+1] + bias[n0+1];
                v.z = acc[ih*4+i][jh*4+2] + bias[n0+2];
                v.w = acc[ih*4+i][jh*4+3] + bias[n0+3];
                *(float4*)&dst[(((size_t)(bb*NH + h))*SEQ + s)*HD + d] = v;
            }
        }
}

// ---------------------------------------------------------------------------
// Flash attention, fp32, causal. One block per (b,h,q-tile of 64).
// 256 threads: thread = (rg=tid/16 -> 4 q-rows, cg=tid%16 -> 4 cols).
// sKt holds K transposed [d][c]; after S-phase it is reused as P [r][c].
// Row reductions via 16-lane __shfl_xor within half-warps.
// ---------------------------------------------------------------------------
__global__ __launch_bounds__(256) void attn_kernel()
{
    __shared__ float sQ [64*64];
    __shared__ float sKt[64*64];     // [d][c]; aliased as sP [r][c] after S
    __shared__ float sV [64*64];     // [c][d]
    float* sP = sKt;

    const int tid = threadIdx.x;
    const int cg = tid & 15, rg = tid >> 4;
    const int rb = rg << 2, cb = cg << 2;
    const int qt = blockIdx.x, bh = blockIdx.y;
    const int q0 = qt * 64;
    const size_t base = (size_t)bh * SEQ * HD;
    const float* Qg = g_q + base;
    const float* Kg = g_k + base;
    const float* Vg = g_v + base;

    // Load Q tile once, pre-scaled by 1/sqrt(D)=0.125
#pragma unroll
    for (int it = 0; it < 4; it++) {
        int idx = it*256 + tid;
        int r = idx >> 4, f = (idx & 15) << 2;
        float4 v = *(const float4*)&Qg[(size_t)(q0 + r)*HD + f];
        v.x *= 0.125f; v.y *= 0.125f; v.z *= 0.125f; v.w *= 0.125f;
        *(float4*)&sQ[r*64 + f] = v;
    }

    float m_run[4], l_run[4], oacc[4][4];
#pragma unroll
    for (int ri = 0; ri < 4; ri++) {
        m_run[ri] = NEG_BIG; l_run[ri] = 0.f;
#pragma unroll
        for (int j = 0; j < 4; j++) oacc[ri][j] = 0.f;
    }

    for (int t = 0; t <= qt; t++) {
        // K tile, transposed into sKt[d][c]. Gmem side is strided (L2-served);
        // smem stores are conflict-free (c across lanes).
#pragma unroll
        for (int it = 0; it < 4; it++) {
            int idx = it*256 + tid;
            int c = idx & 63, d0 = (idx >> 6) << 2;
            float4 kv = *(const float4*)&Kg[(size_t)(t*64 + c)*HD + d0];
            sKt[(d0+0)*64 + c] = kv.x;
            sKt[(d0+1)*64 + c] = kv.y;
            sKt[(d0+2)*64 + c] = kv.z;
            sKt[(d0+3)*64 + c] = kv.w;
        }
        // V tile, row-major
#pragma unroll
        for (int it = 0; it < 4; it++) {
            int idx = it*256 + tid;
            int r = idx >> 4, f = (idx & 15) << 2;
            *(float4*)&sV[r*64 + f] = *(const float4*)&Vg[(size_t)(t*64 + r)*HD + f];
        }
        __syncthreads();

        // S = Q K^T (scaled), 4x4 per thread
        float sacc[4][4];
#pragma unroll
        for (int ri = 0; ri < 4; ri++)
#pragma unroll
            for (int cj = 0; cj < 4; cj++) sacc[ri][cj] = 0.f;

#pragma unroll
        for (int d0 = 0; d0 < 64; d0 += 4) {
            float q4[4][4];
#pragma unroll
            for (int ri = 0; ri < 4; ri++) {
                float4 t4 = *(const float4*)&sQ[(rb+ri)*64 + d0];
                q4[ri][0]=t4.x; q4[ri][1]=t4.y; q4[ri][2]=t4.z; q4[ri][3]=t4.w;
            }
#pragma unroll
            for (int dd = 0; dd < 4; dd++) {
                float4 k4 = *(const float4*)&sKt[(d0+dd)*64 + cb];
#pragma unroll
                for (int ri = 0; ri < 4; ri++) {
                    sacc[ri][0] = fmaf(q4[ri][dd], k4.x, sacc[ri][0]);
                    sacc[ri][1] = fmaf(q4[ri][dd], k4.y, sacc[ri][1]);
                    sacc[ri][2] = fmaf(q4[ri][dd], k4.z, sacc[ri][2]);
                    sacc[ri][3] = fmaf(q4[ri][dd], k4.w, sacc[ri][3]);
                }
            }
        }

        if (t == qt) {   // causal mask on diagonal tile
#pragma unroll
            for (int ri = 0; ri < 4; ri++)
#pragma unroll
                for (int cj = 0; cj < 4; cj++)
                    if (cb + cj > rb + ri) sacc[ri][cj] = NEG_BIG;
        }

        // Online softmax; rows are shared by 16 consecutive lanes (half-warp)
        float p[4][4];
#pragma unroll
        for (int ri = 0; ri < 4; ri++) {
            float tm = fmaxf(fmaxf(sacc[ri][0], sacc[ri][1]),
                             fmaxf(sacc[ri][2], sacc[ri][3]));
#pragma unroll
            for (int off = 8; off >= 1; off >>= 1)
                tm = fmaxf(tm, __shfl_xor_sync(0xffffffffu, tm, off));
            const float mnew = fmaxf(m_run[ri], tm);
            const float corr = __expf(m_run[ri] - mnew);
            float ps = 0.f;
#pragma unroll
            for (int cj = 0; cj < 4; cj++) {
                p[ri][cj] = __expf(sacc[ri][cj] - mnew);
                ps += p[ri][cj];
            }
#pragma unroll
            for (int off = 8; off >= 1; off >>= 1)
                ps += __shfl_xor_sync(0xffffffffu, ps, off);
            l_run[ri] = l_run[ri] * corr + ps;
            m_run[ri] = mnew;
#pragma unroll
            for (int j = 0; j < 4; j++) oacc[ri][j] *= corr;
        }
        __syncthreads();                       // all done reading sKt
#pragma unroll
        for (int ri = 0; ri < 4; ri++)
            *(float4*)&sP[(rb+ri)*64 + cb] =
                make_float4(p[ri][0], p[ri][1], p[ri][2], p[ri][3]);
        __syncthreads();                       // sP ready

        // O += P V
#pragma unroll
        for (int c0 = 0; c0 < 64; c0 += 4) {
            float pr[4][4];
#pragma unroll
            for (int ri = 0; ri < 4; ri++) {
                float4 t4 = *(const float4*)&sP[(rb+ri)*64 + c0];
                pr[ri][0]=t4.x; pr[ri][1]=t4.y; pr[ri][2]=t4.z; pr[ri][3]=t4.w;
            }
#pragma unroll
            for (int cc = 0; cc < 4; cc++) {
                float4 v4 = *(const float4*)&sV[(c0+cc)*64 + cb];
#pragma unroll
                for (int ri = 0; ri < 4; ri++) {
                    oacc[ri][0] = fmaf(pr[ri][cc], v4.x, oacc[ri][0]);
                    oacc[ri][1] = fmaf(pr[ri][cc], v4.y, oacc[ri][1]);
                    oacc[ri][2] = fmaf(pr[ri][cc], v4.z, oacc[ri][2]);
                    oacc[ri][3] = fmaf(pr[ri][cc], v4.w, oacc[ri][3]);
                }
            }
        }
        __syncthreads();                       // done with sP/sV before reload
    }

    // Normalize + write merged-head layout [B*S, E]
    const int b = bh >> 4, h = bh & 15;
#pragma unroll
    for (int ri = 0; ri < 4; ri++) {
        const float inv = 1.0f / l_run[ri];
        float4 o;
        o.x = oacc[ri][0]*inv; o.y = oacc[ri][1]*inv;
        o.z = oacc[ri][2]*inv; o.w = oacc[ri][3]*inv;
        const int row = q0 + rb + ri;
        *(float4*)&g_y[((size_t)(b*SEQ + row))*EMB + h*HD + cb] = o;
    }
}

// ---------------------------------------------------------------------------
// Output projection: g_y[8192,1024] @ w_proj[1024,1024] + b -> out
// ---------------------------------------------------------------------------
__global__ __launch_bounds__(256) void proj_gemm_kernel(
    const float* __restrict__ W, const float* __restrict__ bias,
    float* __restrict__ out)
{
    __shared__ float As[8][132];
    __shared__ float Bs[8][128];
    const int tid = threadIdx.x;
    const int tx = tid & 15, ty = tid >> 4;
    const int bm = blockIdx.y * 128, bn = blockIdx.x * 128;

    float acc[8][8];
#pragma unroll
    for (int i = 0; i < 8; i++)
#pragma unroll
        for (int j = 0; j < 8; j++) acc[i][j] = 0.f;

    const int ar = tid >> 1, ac = (tid & 1) << 2;
    const int br = tid >> 5, bc = (tid & 31) << 2;
    const float* Ap = g_y + (size_t)(bm + ar) * EMB + ac;
    const float* Wp = W + (size_t)br * EMB + bn + bc;

    for (int k0 = 0; k0 < EMB; k0 += 8) {
        float4 av = *(const float4*)(Ap + k0);
        As[ac+0][ar] = av.x; As[ac+1][ar] = av.y;
        As[ac+2][ar] = av.z; As[ac+3][ar] = av.w;
        *(float4*)&Bs[br][bc] = *(const float4*)(Wp + (size_t)k0 * EMB);
        __syncthreads();
#pragma unroll
        for (int k = 0; k < 8; k++) {
            float a[8], b[8];
            float4 t;
            t = *(const float4*)&As[k][ty*4];      a[0]=t.x; a[1]=t.y; a[2]=t.z; a[3]=t.w;
            t = *(const float4*)&As[k][64+ty*4];   a[4]=t.x; a[5]=t.y; a[6]=t.z; a[7]=t.w;
            t = *(const float4*)&Bs[k][tx*4];      b[0]=t.x; b[1]=t.y; b[2]=t.z; b[3]=t.w;
            t = *(const float4*)&Bs[k][64+tx*4];   b[4]=t.x; b[5]=t.y; b[6]=t.z; b[7]=t.w;
#pragma unroll
            for (int i = 0; i < 8; i++)
#pragma unroll
                for (int j = 0; j < 8; j++)
                    acc[i][j] = fmaf(a[i], b[j], acc[i][j]);
        }
        __syncthreads();
    }

#pragma unroll
    for (int ih = 0; ih < 2; ih++)
#pragma unroll
        for (int i = 0; i < 4; i++) {
            const int m = bm + ih*64 + ty*4 + i;
#pragma unroll
            for (int jh = 0; jh < 2; jh++) {
                const int n0 = bn + jh*64 + tx*4;
                float4 v;
                v.x = acc[ih*4+i][jh*4+0] + bias[n0+0];
                v.y = acc[ih*4+i][jh*4+1] + bias[n0+1];
                v.z = acc[ih*4+i][jh*4+2] + bias[n0+2];
                v.w = acc[ih*4+i][jh*4+3] + bias[n0+3];
                *(float4*)&out[(size_t)m*EMB + n0] = v;
            }
        }
}

// ---------------------------------------------------------------------------
extern "C" void kernel_launch(void* const* d_in, const int* in_sizes, int n_in,
                              void* d_out, int out_size)
{
    const float* x      = (const float*)d_in[0];
    const float* w_qkv  = (const float*)d_in[1];
    const float* b_qkv  = (const float*)d_in[2];
    const float* w_proj = (const float*)d_in[3];
    const float* b_proj = (const float*)d_in[4];
    float* out = (float*)d_out;

    qkv_gemm_kernel<<<dim3(NQKV/128, MTOT/128), 256>>>(x, w_qkv, b_qkv);
    attn_kernel    <<<dim3(SEQ/64,   BSZ*NH  ), 256>>>();
    proj_gemm_kernel<<<dim3(EMB/128, MTOT/128), 256>>>(w_proj, b_proj, out);
}

// round 4
// speedup vs baseline: 2.8982x; 2.8982x over previous
#include <cuda_runtime.h>
#include <cstdint>

#define BSZ 4
#define SEQ 2048
#define EMB 1024
#define NH  16
#define HD  64
#define MTOT (BSZ*SEQ)       /* 8192 */
#define NQKV (3*EMB)         /* 3072 */
#define NEG_BIG (-3.0e38f)

// Scratch (device globals: allocation-free per harness rules)
__device__ float g_q[(size_t)BSZ*NH*SEQ*HD];   // [B,H,S,D]
__device__ float g_k[(size_t)BSZ*NH*SEQ*HD];
__device__ float g_v[(size_t)BSZ*NH*SEQ*HD];
__device__ float g_y[(size_t)MTOT*EMB];        // attention output, [B*S, E]

__device__ __forceinline__ unsigned f2t(float f) {
    unsigned r;
    asm("cvt.rna.tf32.f32 %0, %1;" : "=r"(r) : "f"(f));
    return r;
}

// D = A(16x8) * B(8x8) + D, tf32, fp32 accum
__device__ __forceinline__ void mma8(float* c, const unsigned* a,
                                     unsigned b0, unsigned b1) {
    asm volatile(
        "mma.sync.aligned.m16n8k8.row.col.f32.tf32.tf32.f32 "
        "{%0,%1,%2,%3}, {%4,%5,%6,%7}, {%8,%9}, {%0,%1,%2,%3};"
        : "+f"(c[0]), "+f"(c[1]), "+f"(c[2]), "+f"(c[3])
        : "r"(a[0]), "r"(a[1]), "r"(a[2]), "r"(a[3]), "r"(b0), "r"(b1));
}

// ---------------------------------------------------------------------------
// tf32 MMA GEMM mainloop: C[128,128] tile, BK=16, 8 warps (2x4), warp=64x32.
// As stride 20 / Bs stride 136 -> conflict-free fragment LDS.
// Double-buffered smem: one __syncthreads per K-iter.
// ---------------------------------------------------------------------------
#define AS_STR 20
#define BS_STR 136

struct GemmFrag {
    float acc[4][4][4];     // [mt][nt][reg]
};

template<int N>
__device__ __forceinline__ void gemm_mainloop(
    const float* __restrict__ A, const float* __restrict__ W,
    int bm, int bn, unsigned* As, unsigned* Bs, GemmFrag& fr)
{
    const int tid = threadIdx.x;
    const int warp = tid >> 5, lane = tid & 31;
    const int wm = warp >> 2, wn = warp & 3;
    const int g = lane >> 2, t = lane & 3;

#pragma unroll
    for (int mt = 0; mt < 4; mt++)
#pragma unroll
        for (int nt = 0; nt < 4; nt++)
#pragma unroll
            for (int r = 0; r < 4; r++) fr.acc[mt][nt][r] = 0.f;

    const int ar = tid >> 2, ac = (tid & 3) << 2;      // A: rows ar, ar+64
    const int br = tid >> 5, bc = (tid & 31) << 2;     // B: rows br, br+8
    const float* Ap0 = A + (size_t)(bm + ar) * EMB + ac;
    const float* Ap1 = A + (size_t)(bm + ar + 64) * EMB + ac;
    const float* Wp0 = W + (size_t)br * N + bn + bc;
    const float* Wp1 = W + (size_t)(br + 8) * N + bn + bc;

    // prologue: tile 0 into buf 0
    {
        float4 a0 = *(const float4*)(Ap0);
        float4 a1 = *(const float4*)(Ap1);
        float4 b0 = *(const float4*)(Wp0);
        float4 b1 = *(const float4*)(Wp1);
        unsigned* Asb = As;
        Asb[ar*AS_STR + ac+0] = f2t(a0.x); Asb[ar*AS_STR + ac+1] = f2t(a0.y);
        Asb[ar*AS_STR + ac+2] = f2t(a0.z); Asb[ar*AS_STR + ac+3] = f2t(a0.w);
        Asb[(ar+64)*AS_STR + ac+0] = f2t(a1.x); Asb[(ar+64)*AS_STR + ac+1] = f2t(a1.y);
        Asb[(ar+64)*AS_STR + ac+2] = f2t(a1.z); Asb[(ar+64)*AS_STR + ac+3] = f2t(a1.w);
        unsigned* Bsb = Bs;
        Bsb[br*BS_STR + bc+0] = f2t(b0.x); Bsb[br*BS_STR + bc+1] = f2t(b0.y);
        Bsb[br*BS_STR + bc+2] = f2t(b0.z); Bsb[br*BS_STR + bc+3] = f2t(b0.w);
        Bsb[(br+8)*BS_STR + bc+0] = f2t(b1.x); Bsb[(br+8)*BS_STR + bc+1] = f2t(b1.y);
        Bsb[(br+8)*BS_STR + bc+2] = f2t(b1.z); Bsb[(br+8)*BS_STR + bc+3] = f2t(b1.w);
    }
    __syncthreads();

    int buf = 0;
    for (int k0 = 0; k0 < EMB; k0 += 16) {
        const int nxt = k0 + 16;
        float4 pa0, pa1, pb0, pb1;
        if (nxt < EMB) {
            pa0 = *(const float4*)(Ap0 + nxt);
            pa1 = *(const float4*)(Ap1 + nxt);
            pb0 = *(const float4*)(Wp0 + (size_t)nxt * N);
            pb1 = *(const float4*)(Wp1 + (size_t)nxt * N);
        }
        // compute current buffer
        const unsigned* Asb = As + buf * (128*AS_STR);
        const unsigned* Bsb = Bs + buf * (16*BS_STR);
#pragma unroll
        for (int ks = 0; ks < 2; ks++) {
            const int k = ks * 8;
            unsigned afr[4][4];
#pragma unroll
            for (int mt = 0; mt < 4; mt++) {
                const int base = (wm*64 + mt*16 + g)*AS_STR + k + t;
                afr[mt][0] = Asb[base];
                afr[mt][1] = Asb[base + 8*AS_STR];
                afr[mt][2] = Asb[base + 4];
                afr[mt][3] = Asb[base + 8*AS_STR + 4];
            }
#pragma unroll
            for (int nt = 0; nt < 4; nt++) {
                const int col = wn*32 + nt*8 + g;
                unsigned b0 = Bsb[(k + t)*BS_STR + col];
                unsigned b1 = Bsb[(k + 4 + t)*BS_STR + col];
#pragma unroll
                for (int mt = 0; mt < 4; mt++)
                    mma8(fr.acc[mt][nt], afr[mt], b0, b1);
            }
        }
        if (nxt < EMB) {
            unsigned* Asn = As + (buf^1) * (128*AS_STR);
            unsigned* Bsn = Bs + (buf^1) * (16*BS_STR);
            Asn[ar*AS_STR + ac+0] = f2t(pa0.x); Asn[ar*AS_STR + ac+1] = f2t(pa0.y);
            Asn[ar*AS_STR + ac+2] = f2t(pa0.z); Asn[ar*AS_STR + ac+3] = f2t(pa0.w);
            Asn[(ar+64)*AS_STR + ac+0] = f2t(pa1.x); Asn[(ar+64)*AS_STR + ac+1] = f2t(pa1.y);
            Asn[(ar+64)*AS_STR + ac+2] = f2t(pa1.z); Asn[(ar+64)*AS_STR + ac+3] = f2t(pa1.w);
            Bsn[br*BS_STR + bc+0] = f2t(pb0.x); Bsn[br*BS_STR + bc+1] = f2t(pb0.y);
            Bsn[br*BS_STR + bc+2] = f2t(pb0.z); Bsn[br*BS_STR + bc+3] = f2t(pb0.w);
            Bsn[(br+8)*BS_STR + bc+0] = f2t(pb1.x); Bsn[(br+8)*BS_STR + bc+1] = f2t(pb1.y);
            Bsn[(br+8)*BS_STR + bc+2] = f2t(pb1.z); Bsn[(br+8)*BS_STR + bc+3] = f2t(pb1.w);
            __syncthreads();
            buf ^= 1;
        }
    }
}

// ---------------------------------------------------------------------------
// QKV GEMM: x[8192,1024] @ w_qkv[1024,3072] + b, scatter into g_q/g_k/g_v
// ---------------------------------------------------------------------------
__global__ __launch_bounds__(256) void qkv_gemm_kernel(
    const float* __restrict__ A, const float* __restrict__ W,
    const float* __restrict__ bias)
{
    __shared__ unsigned As[2*128*AS_STR];
    __shared__ unsigned Bs[2*16*BS_STR];
    const int bm = blockIdx.y * 128, bn = blockIdx.x * 128;

    GemmFrag fr;
    gemm_mainloop<NQKV>(A, W, bm, bn, As, Bs, fr);

    const int tid = threadIdx.x;
    const int warp = tid >> 5, lane = tid & 31;
    const int wm = warp >> 2, wn = warp & 3;
    const int g = lane >> 2, t = lane & 3;

#pragma unroll
    for (int mt = 0; mt < 4; mt++) {
#pragma unroll
        for (int nt = 0; nt < 4; nt++) {
            const int n0 = bn + wn*32 + nt*8 + 2*t;
            const int sect = n0 >> 10;
            const int e = n0 & (EMB-1);
            const int h = e >> 6, d = e & 63;
            float* dst = (sect == 0) ? g_q : (sect == 1) ? g_k : g_v;
            const float bx = bias[n0], by = bias[n0+1];
#pragma unroll
            for (int half = 0; half < 2; half++) {
                const int m = bm + wm*64 + mt*16 + g + half*8;
                const int bb = m >> 11;
                const int s  = m & (SEQ-1);
                float2 v;
                v.x = fr.acc[mt][nt][half*2+0] + bx;
                v.y = fr.acc[mt][nt][half*2+1] + by;
                *(float2*)&dst[(((size_t)(bb*NH + h))*SEQ + s)*HD + d] = v;
            }
        }
    }
}

// ---------------------------------------------------------------------------
// Proj GEMM: g_y[8192,1024] @ w_proj[1024,1024] + b -> out
// ---------------------------------------------------------------------------
__global__ __launch_bounds__(256) void proj_gemm_kernel(
    const float* __restrict__ W, const float* __restrict__ bias,
    float* __restrict__ out)
{
    __shared__ unsigned As[2*128*AS_STR];
    __shared__ unsigned Bs[2*16*BS_STR];
    const int bm = blockIdx.y * 128, bn = blockIdx.x * 128;

    GemmFrag fr;
    gemm_mainloop<EMB>(g_y, W, bm, bn, As, Bs, fr);

    const int tid = threadIdx.x;
    const int warp = tid >> 5, lane = tid & 31;
    const int wm = warp >> 2, wn = warp & 3;
    const int g = lane >> 2, t = lane & 3;

#pragma unroll
    for (int mt = 0; mt < 4; mt++) {
#pragma unroll
        for (int nt = 0; nt < 4; nt++) {
            const int n0 = bn + wn*32 + nt*8 + 2*t;
            const float bx = bias[n0], by = bias[n0+1];
#pragma unroll
            for (int half = 0; half < 2; half++) {
                const int m = bm + wm*64 + mt*16 + g + half*8;
                float2 v;
                v.x = fr.acc[mt][nt][half*2+0] + bx;
                v.y = fr.acc[mt][nt][half*2+1] + by;
                *(float2*)&out[(size_t)m*EMB + n0] = v;
            }
        }
    }
}

// ---------------------------------------------------------------------------
// Flash attention, tf32 MMA. CTA = 128 q-rows (8 warps x 16), KV tiles of 64.
// Dynamic smem (uint/tf32): sQ[128][68], sK[64][68], sV[64][72], sP[128][68]
// ---------------------------------------------------------------------------
#define SQ_OFF 0
#define SK_OFF 8704
#define SV_OFF 13056
#define SP_OFF 17664
#define ATTN_SMEM_BYTES (26368*4)

__global__ __launch_bounds__(256) void attn_kernel()
{
    extern __shared__ unsigned sm[];
    unsigned* SQ = sm + SQ_OFF;
    unsigned* SK = sm + SK_OFF;
    unsigned* SV = sm + SV_OFF;
    unsigned* SP = sm + SP_OFF;

    const int tid = threadIdx.x;
    const int w = tid >> 5, lane = tid & 31;
    const int g = lane >> 2, t = lane & 3;
    const int qt = blockIdx.x, bh = blockIdx.y;
    const int q0 = qt * 128;
    const int qrow = w * 16;                     // warp strip within CTA
    const size_t base = (size_t)bh * SEQ * HD;
    const float* Qg = g_q + base;
    const float* Kg = g_k + base;
    const float* Vg = g_v + base;

    // Q tile (pre-scaled by 1/8, tf32)
#pragma unroll
    for (int it = 0; it < 8; it++) {
        int idx = it*256 + tid;
        int r = idx >> 4, c = (idx & 15) << 2;
        float4 v = *(const float4*)&Qg[(size_t)(q0 + r)*HD + c];
        SQ[r*68 + c+0] = f2t(v.x * 0.125f);
        SQ[r*68 + c+1] = f2t(v.y * 0.125f);
        SQ[r*68 + c+2] = f2t(v.z * 0.125f);
        SQ[r*68 + c+3] = f2t(v.w * 0.125f);
    }

    float m0 = NEG_BIG, m1 = NEG_BIG, l0 = 0.f, l1 = 0.f;
    float oacc[8][4];
#pragma unroll
    for (int nt = 0; nt < 8; nt++)
#pragma unroll
        for (int r = 0; r < 4; r++) oacc[nt][r] = 0.f;

    const int ntiles = 2*qt + 2;
    for (int tk = 0; tk < ntiles; tk++) {
        // K tile [kv][d] and V tile [kv][d]
#pragma unroll
        for (int it = 0; it < 4; it++) {
            int idx = it*256 + tid;
            int r = idx >> 4, c = (idx & 15) << 2;
            float4 kv = *(const float4*)&Kg[(size_t)(tk*64 + r)*HD + c];
            SK[r*68 + c+0] = f2t(kv.x); SK[r*68 + c+1] = f2t(kv.y);
            SK[r*68 + c+2] = f2t(kv.z); SK[r*68 + c+3] = f2t(kv.w);
            float4 vv = *(const float4*)&Vg[(size_t)(tk*64 + r)*HD + c];
            SV[r*72 + c+0] = f2t(vv.x); SV[r*72 + c+1] = f2t(vv.y);
            SV[r*72 + c+2] = f2t(vv.z); SV[r*72 + c+3] = f2t(vv.w);
        }
        __syncthreads();

        // S = Q K^T   (16x64 per warp)
        float sacc[8][4];
#pragma unroll
        for (int nt = 0; nt < 8; nt++)
#pragma unroll
            for (int r = 0; r < 4; r++) sacc[nt][r] = 0.f;

#pragma unroll
        for (int dk = 0; dk < 8; dk++) {
            const int k = dk * 8;
            unsigned afr[4];
            const int ab = (qrow + g)*68 + k + t;
            afr[0] = SQ[ab];
            afr[1] = SQ[ab + 8*68];
            afr[2] = SQ[ab + 4];
            afr[3] = SQ[ab + 8*68 + 4];
#pragma unroll
            for (int nt = 0; nt < 8; nt++) {
                const int kb = (nt*8 + g)*68 + k + t;
                unsigned b0 = SK[kb];
                unsigned b1 = SK[kb + 4];
                mma8(sacc[nt], afr, b0, b1);
            }
        }

        const int row0 = q0 + qrow + g;
        const int row1 = row0 + 8;
        if (tk >= 2*qt) {    // partially-masked tiles
#pragma unroll
            for (int nt = 0; nt < 8; nt++) {
                const int col = tk*64 + nt*8 + 2*t;
                if (col   > row0) sacc[nt][0] = NEG_BIG;
                if (col+1 > row0) sacc[nt][1] = NEG_BIG;
                if (col   > row1) sacc[nt][2] = NEG_BIG;
                if (col+1 > row1) sacc[nt][3] = NEG_BIG;
            }
        }

        // online softmax (rows g / g+8, shared by 4-lane groups)
        float mx0 = NEG_BIG, mx1 = NEG_BIG;
#pragma unroll
        for (int nt = 0; nt < 8; nt++) {
            mx0 = fmaxf(mx0, fmaxf(sacc[nt][0], sacc[nt][1]));
            mx1 = fmaxf(mx1, fmaxf(sacc[nt][2], sacc[nt][3]));
        }
        mx0 = fmaxf(mx0, __shfl_xor_sync(0xffffffffu, mx0, 1));
        mx0 = fmaxf(mx0, __shfl_xor_sync(0xffffffffu, mx0, 2));
        mx1 = fmaxf(mx1, __shfl_xor_sync(0xffffffffu, mx1, 1));
        mx1 = fmaxf(mx1, __shfl_xor_sync(0xffffffffu, mx1, 2));
        const float mn0 = fmaxf(m0, mx0), mn1 = fmaxf(m1, mx1);
        const float c0 = __expf(m0 - mn0), c1 = __expf(m1 - mn1);
        float s0 = 0.f, s1 = 0.f;
#pragma unroll
        for (int nt = 0; nt < 8; nt++) {
            sacc[nt][0] = __expf(sacc[nt][0] - mn0);
            sacc[nt][1] = __expf(sacc[nt][1] - mn0);
            sacc[nt][2] = __expf(sacc[nt][2] - mn1);
            sacc[nt][3] = __expf(sacc[nt][3] - mn1);
            s0 += sacc[nt][0] + sacc[nt][1];
            s1 += sacc[nt][2] + sacc[nt][3];
        }
        s0 += __shfl_xor_sync(0xffffffffu, s0, 1);
        s0 += __shfl_xor_sync(0xffffffffu, s0, 2);
        s1 += __shfl_xor_sync(0xffffffffu, s1, 1);
        s1 += __shfl_xor_sync(0xffffffffu, s1, 2);
        l0 = l0 * c0 + s0;  m0 = mn0;
        l1 = l1 * c1 + s1;  m1 = mn1;
#pragma unroll
        for (int nt = 0; nt < 8; nt++) {
            oacc[nt][0] *= c0; oacc[nt][1] *= c0;
            oacc[nt][2] *= c1; oacc[nt][3] *= c1;
        }

        // P -> smem (warp-private strip), tf32
#pragma unroll
        for (int nt = 0; nt < 8; nt++) {
            uint2 p0 = make_uint2(f2t(sacc[nt][0]), f2t(sacc[nt][1]));
            uint2 p1 = make_uint2(f2t(sacc[nt][2]), f2t(sacc[nt][3]));
            *(uint2*)&SP[(qrow + g)*68 + nt*8 + 2*t]     = p0;
            *(uint2*)&SP[(qrow + 8 + g)*68 + nt*8 + 2*t] = p1;
        }
        __syncwarp();

        // O += P V
#pragma unroll
        for (int kk = 0; kk < 8; kk++) {
            const int k = kk * 8;
            unsigned afr[4];
            const int pb = (qrow + g)*68 + k + t;
            afr[0] = SP[pb];
            afr[1] = SP[pb + 8*68];
            afr[2] = SP[pb + 4];
            afr[3] = SP[pb + 8*68 + 4];
#pragma unroll
            for (int nt = 0; nt < 8; nt++) {
                unsigned b0 = SV[(k + t)*72 + nt*8 + g];
                unsigned b1 = SV[(k + 4 + t)*72 + nt*8 + g];
                mma8(oacc[nt], afr, b0, b1);
            }
        }
        __syncthreads();   // done with SK/SV before next tile load
    }

    // normalize + write merged-head layout [B*S, E]
    const int b = bh >> 4, h = bh & 15;
    const float i0 = 1.0f / l0, i1 = 1.0f / l1;
    const int r0 = q0 + qrow + g;
#pragma unroll
    for (int nt = 0; nt < 8; nt++) {
        const int col = h*64 + nt*8 + 2*t;
        float2 o0, o1;
        o0.x = oacc[nt][0]*i0; o0.y = oacc[nt][1]*i0;
        o1.x = oacc[nt][2]*i1; o1.y = oacc[nt][3]*i1;
        *(float2*)&g_y[((size_t)(b*SEQ + r0))*EMB + col]     = o0;
        *(float2*)&g_y[((size_t)(b*SEQ + r0 + 8))*EMB + col] = o1;
    }
}

// ---------------------------------------------------------------------------
extern "C" void kernel_launch(void* const* d_in, const int* in_sizes, int n_in,
                              void* d_out, int out_size)
{
    const float* x      = (const float*)d_in[0];
    const float* w_qkv  = (const float*)d_in[1];
    const float* b_qkv  = (const float*)d_in[2];
    const float* w_proj = (const float*)d_in[3];
    const float* b_proj = (const float*)d_in[4];
    float* out = (float*)d_out;

    cudaFuncSetAttribute(attn_kernel,
                         cudaFuncAttributeMaxDynamicSharedMemorySize,
                         ATTN_SMEM_BYTES);

    qkv_gemm_kernel<<<dim3(NQKV/128, MTOT/128), 256>>>(x, w_qkv, b_qkv);
    attn_kernel<<<dim3(SEQ/128, BSZ*NH), 256, ATTN_SMEM_BYTES>>>();
    proj_gemm_kernel<<<dim3(EMB/128, MTOT/128), 256>>>(w_proj, b_proj, out);
}

// round 5
// speedup vs baseline: 3.1602x; 1.0904x over previous
#include <cuda_runtime.h>
#include <cstdint>

#define BSZ 4
#define SEQ 2048
#define EMB 1024
#define NH  16
#define HD  64
#define MTOT (BSZ*SEQ)       /* 8192 */
#define NQKV (3*EMB)         /* 3072 */
#define NEG_BIG (-3.0e38f)
#define LOG2E 1.4426950408889634f

// Scratch (device globals: allocation-free per harness rules)
__device__ float g_q[(size_t)BSZ*NH*SEQ*HD];   // [B,H,S,D]
__device__ float g_k[(size_t)BSZ*NH*SEQ*HD];
__device__ float g_v[(size_t)BSZ*NH*SEQ*HD];
__device__ float g_y[(size_t)MTOT*EMB];        // attention output, [B*S, E]

__device__ __forceinline__ unsigned f2t(float f) {
    unsigned r;
    asm("cvt.rna.tf32.f32 %0, %1;" : "=r"(r) : "f"(f));
    return r;
}
__device__ __forceinline__ float ex2(float x) {
    float r;
    asm("ex2.approx.ftz.f32 %0, %1;" : "=f"(r) : "f"(x));
    return r;
}

// D = A(16x8) * B(8x8) + D, tf32, fp32 accum
__device__ __forceinline__ void mma8(float* c, const unsigned* a,
                                     unsigned b0, unsigned b1) {
    asm volatile(
        "mma.sync.aligned.m16n8k8.row.col.f32.tf32.tf32.f32 "
        "{%0,%1,%2,%3}, {%4,%5,%6,%7}, {%8,%9}, {%0,%1,%2,%3};"
        : "+f"(c[0]), "+f"(c[1]), "+f"(c[2]), "+f"(c[3])
        : "r"(a[0]), "r"(a[1]), "r"(a[2]), "r"(a[3]), "r"(b0), "r"(b1));
}

// ---------------------------------------------------------------------------
// tf32 MMA GEMM mainloop: C[128,128] tile, BK=16, 4 warps (2x2), warp=64x64.
// 128 threads. As stride 20 / Bs stride 136 -> conflict-free fragment LDS
// (verified layouts). Double-buffered smem: one __syncthreads per K-slab.
// ---------------------------------------------------------------------------
#define AS_STR 20
#define BS_STR 136

struct GemmFrag {
    float acc[4][8][4];     // [mt][nt][reg]  (64x64 per warp)
};

template<int N>
__device__ __forceinline__ void gemm_mainloop(
    const float* __restrict__ A, const float* __restrict__ W,
    int bm, int bn, unsigned* As, unsigned* Bs, GemmFrag& fr)
{
    const int tid = threadIdx.x;
    const int warp = tid >> 5, lane = tid & 31;
    const int wm = warp >> 1, wn = warp & 1;
    const int g = lane >> 2, t = lane & 3;

#pragma unroll
    for (int mt = 0; mt < 4; mt++)
#pragma unroll
        for (int nt = 0; nt < 8; nt++)
#pragma unroll
            for (int r = 0; r < 4; r++) fr.acc[mt][nt][r] = 0.f;

    const int ar = tid >> 2, ac = (tid & 3) << 2;  // A rows ar+32p, cols ac..ac+3
    const int br = tid >> 5, bc = lane << 2;       // B rows br+4p, cols bc..bc+3
    const float* Ap = A + (size_t)(bm + ar) * EMB + ac;
    const float* Wp = W + (size_t)br * N + bn + bc;

    // prologue: slab 0 into buf 0
#pragma unroll
    for (int p = 0; p < 4; p++) {
        float4 a = *(const float4*)(Ap + (size_t)(p*32) * EMB);
        *(uint4*)&As[(ar + p*32)*AS_STR + ac] =
            make_uint4(f2t(a.x), f2t(a.y), f2t(a.z), f2t(a.w));
        float4 b = *(const float4*)(Wp + (size_t)(p*4) * N);
        *(uint4*)&Bs[(br + p*4)*BS_STR + bc] =
            make_uint4(f2t(b.x), f2t(b.y), f2t(b.z), f2t(b.w));
    }
    __syncthreads();

    int buf = 0;
    for (int k0 = 0; k0 < EMB; k0 += 16) {
        const int nxt = k0 + 16;
        float4 pa[4], pb[4];
        if (nxt < EMB) {
#pragma unroll
            for (int p = 0; p < 4; p++) {
                pa[p] = *(const float4*)(Ap + (size_t)(p*32) * EMB + nxt);
                pb[p] = *(const float4*)(Wp + (size_t)(nxt + p*4) * N);
            }
        }
        const unsigned* Asb = As + buf * (128*AS_STR);
        const unsigned* Bsb = Bs + buf * (16*BS_STR);
#pragma unroll
        for (int ks = 0; ks < 2; ks++) {
            const int k = ks * 8;
            unsigned afr[4][4];
#pragma unroll
            for (int mt = 0; mt < 4; mt++) {
                const int base = (wm*64 + mt*16 + g)*AS_STR + k + t;
                afr[mt][0] = Asb[base];
                afr[mt][1] = Asb[base + 8*AS_STR];
                afr[mt][2] = Asb[base + 4];
                afr[mt][3] = Asb[base + 8*AS_STR + 4];
            }
#pragma unroll
            for (int nt = 0; nt < 8; nt++) {
                const int col = wn*64 + nt*8 + g;
                unsigned b0 = Bsb[(k + t)*BS_STR + col];
                unsigned b1 = Bsb[(k + 4 + t)*BS_STR + col];
#pragma unroll
                for (int mt = 0; mt < 4; mt++)
                    mma8(fr.acc[mt][nt], afr[mt], b0, b1);
            }
        }
        if (nxt < EMB) {
            unsigned* Asn = As + (buf^1) * (128*AS_STR);
            unsigned* Bsn = Bs + (buf^1) * (16*BS_STR);
#pragma unroll
            for (int p = 0; p < 4; p++) {
                *(uint4*)&Asn[(ar + p*32)*AS_STR + ac] =
                    make_uint4(f2t(pa[p].x), f2t(pa[p].y), f2t(pa[p].z), f2t(pa[p].w));
                *(uint4*)&Bsn[(br + p*4)*BS_STR + bc] =
                    make_uint4(f2t(pb[p].x), f2t(pb[p].y), f2t(pb[p].z), f2t(pb[p].w));
            }
            __syncthreads();
            buf ^= 1;
        }
    }
}

// ---------------------------------------------------------------------------
// QKV GEMM: x[8192,1024] @ w_qkv[1024,3072] + b, scatter into g_q/g_k/g_v
// ---------------------------------------------------------------------------
__global__ __launch_bounds__(128, 2) void qkv_gemm_kernel(
    const float* __restrict__ A, const float* __restrict__ W,
    const float* __restrict__ bias)
{
    __shared__ unsigned As[2*128*AS_STR];
    __shared__ unsigned Bs[2*16*BS_STR];
    const int bm = blockIdx.y * 128, bn = blockIdx.x * 128;

    GemmFrag fr;
    gemm_mainloop<NQKV>(A, W, bm, bn, As, Bs, fr);

    const int tid = threadIdx.x;
    const int warp = tid >> 5, lane = tid & 31;
    const int wm = warp >> 1, wn = warp & 1;
    const int g = lane >> 2, t = lane & 3;

#pragma unroll
    for (int mt = 0; mt < 4; mt++) {
#pragma unroll
        for (int nt = 0; nt < 8; nt++) {
            const int n0 = bn + wn*64 + nt*8 + 2*t;
            const int sect = n0 >> 10;
            const int e = n0 & (EMB-1);
            const int h = e >> 6, d = e & 63;
            float* dst = (sect == 0) ? g_q : (sect == 1) ? g_k : g_v;
            const float bx = bias[n0], by = bias[n0+1];
#pragma unroll
            for (int half = 0; half < 2; half++) {
                const int m = bm + wm*64 + mt*16 + g + half*8;
                const int bb = m >> 11;
                const int s  = m & (SEQ-1);
                float2 v;
                v.x = fr.acc[mt][nt][half*2+0] + bx;
                v.y = fr.acc[mt][nt][half*2+1] + by;
                *(float2*)&dst[(((size_t)(bb*NH + h))*SEQ + s)*HD + d] = v;
            }
        }
    }
}

// ---------------------------------------------------------------------------
// Proj GEMM: g_y[8192,1024] @ w_proj[1024,1024] + b -> out
// ---------------------------------------------------------------------------
__global__ __launch_bounds__(128, 2) void proj_gemm_kernel(
    const float* __restrict__ W, const float* __restrict__ bias,
    float* __restrict__ out)
{
    __shared__ unsigned As[2*128*AS_STR];
    __shared__ unsigned Bs[2*16*BS_STR];
    const int bm = blockIdx.y * 128, bn = blockIdx.x * 128;

    GemmFrag fr;
    gemm_mainloop<EMB>(g_y, W, bm, bn, As, Bs, fr);

    const int tid = threadIdx.x;
    const int warp = tid >> 5, lane = tid & 31;
    const int wm = warp >> 1, wn = warp & 1;
    const int g = lane >> 2, t = lane & 3;

#pragma unroll
    for (int mt = 0; mt < 4; mt++) {
#pragma unroll
        for (int nt = 0; nt < 8; nt++) {
            const int n0 = bn + wn*64 + nt*8 + 2*t;
            const float bx = bias[n0], by = bias[n0+1];
#pragma unroll
            for (int half = 0; half < 2; half++) {
                const int m = bm + wm*64 + mt*16 + g + half*8;
                float2 v;
                v.x = fr.acc[mt][nt][half*2+0] + bx;
                v.y = fr.acc[mt][nt][half*2+1] + by;
                *(float2*)&out[(size_t)m*EMB + n0] = v;
            }
        }
    }
}

// ---------------------------------------------------------------------------
// Flash attention, tf32 MMA. CTA = 128 q-rows (8 warps x 16), KV tiles of 64.
// Softmax in log2 domain (scale 0.125*log2e folded into Q; pure ex2.approx).
// Dynamic smem (uint/tf32): sQ[128][68], sK[64][68], sV[64][72], sP[128][68]
// ---------------------------------------------------------------------------
#define SQ_OFF 0
#define SK_OFF 8704
#define SV_OFF 13056
#define SP_OFF 17664
#define ATTN_SMEM_BYTES (26368*4)

__global__ __launch_bounds__(256) void attn_kernel()
{
    extern __shared__ unsigned sm[];
    unsigned* SQ = sm + SQ_OFF;
    unsigned* SK = sm + SK_OFF;
    unsigned* SV = sm + SV_OFF;
    unsigned* SP = sm + SP_OFF;

    const int tid = threadIdx.x;
    const int w = tid >> 5, lane = tid & 31;
    const int g = lane >> 2, t = lane & 3;
    const int qt = blockIdx.x, bh = blockIdx.y;
    const int q0 = qt * 128;
    const int qrow = w * 16;                     // warp strip within CTA
    const size_t base = (size_t)bh * SEQ * HD;
    const float* Qg = g_q + base;
    const float* Kg = g_k + base;
    const float* Vg = g_v + base;

    // Q tile (pre-scaled by 0.125*log2e, tf32)
    const float qs = 0.125f * LOG2E;
#pragma unroll
    for (int it = 0; it < 8; it++) {
        int idx = it*256 + tid;
        int r = idx >> 4, c = (idx & 15) << 2;
        float4 v = *(const float4*)&Qg[(size_t)(q0 + r)*HD + c];
        SQ[r*68 + c+0] = f2t(v.x * qs);
        SQ[r*68 + c+1] = f2t(v.y * qs);
        SQ[r*68 + c+2] = f2t(v.z * qs);
        SQ[r*68 + c+3] = f2t(v.w * qs);
    }

    float m0 = NEG_BIG, m1 = NEG_BIG, l0 = 0.f, l1 = 0.f;
    float oacc[8][4];
#pragma unroll
    for (int nt = 0; nt < 8; nt++)
#pragma unroll
        for (int r = 0; r < 4; r++) oacc[nt][r] = 0.f;

    const int ntiles = 2*qt + 2;
    for (int tk = 0; tk < ntiles; tk++) {
        // K tile [kv][d] and V tile [kv][d]
#pragma unroll
        for (int it = 0; it < 4; it++) {
            int idx = it*256 + tid;
            int r = idx >> 4, c = (idx & 15) << 2;
            float4 kv = *(const float4*)&Kg[(size_t)(tk*64 + r)*HD + c];
            SK[r*68 + c+0] = f2t(kv.x); SK[r*68 + c+1] = f2t(kv.y);
            SK[r*68 + c+2] = f2t(kv.z); SK[r*68 + c+3] = f2t(kv.w);
            float4 vv = *(const float4*)&Vg[(size_t)(tk*64 + r)*HD + c];
            SV[r*72 + c+0] = f2t(vv.x); SV[r*72 + c+1] = f2t(vv.y);
            SV[r*72 + c+2] = f2t(vv.z); SV[r*72 + c+3] = f2t(vv.w);
        }
        __syncthreads();

        // S = Q K^T (log2-scaled), 16x64 per warp
        float sacc[8][4];
#pragma unroll
        for (int nt = 0; nt < 8; nt++)
#pragma unroll
            for (int r = 0; r < 4; r++) sacc[nt][r] = 0.f;

#pragma unroll
        for (int dk = 0; dk < 8; dk++) {
            const int k = dk * 8;
            unsigned afr[4];
            const int ab = (qrow + g)*68 + k + t;
            afr[0] = SQ[ab];
            afr[1] = SQ[ab + 8*68];
            afr[2] = SQ[ab + 4];
            afr[3] = SQ[ab + 8*68 + 4];
#pragma unroll
            for (int nt = 0; nt < 8; nt++) {
                const int kb = (nt*8 + g)*68 + k + t;
                unsigned b0 = SK[kb];
                unsigned b1 = SK[kb + 4];
                mma8(sacc[nt], afr, b0, b1);
            }
        }

        const int row0 = q0 + qrow + g;
        const int row1 = row0 + 8;
        if (tk >= 2*qt) {    // partially-masked tiles
#pragma unroll
            for (int nt = 0; nt < 8; nt++) {
                const int col = tk*64 + nt*8 + 2*t;
                if (col   > row0) sacc[nt][0] = NEG_BIG;
                if (col+1 > row0) sacc[nt][1] = NEG_BIG;
                if (col   > row1) sacc[nt][2] = NEG_BIG;
                if (col+1 > row1) sacc[nt][3] = NEG_BIG;
            }
        }

        // online softmax, log2 domain (rows g / g+8, shared by 4-lane groups)
        float mx0 = NEG_BIG, mx1 = NEG_BIG;
#pragma unroll
        for (int nt = 0; nt < 8; nt++) {
            mx0 = fmaxf(mx0, fmaxf(sacc[nt][0], sacc[nt][1]));
            mx1 = fmaxf(mx1, fmaxf(sacc[nt][2], sacc[nt][3]));
        }
        mx0 = fmaxf(mx0, __shfl_xor_sync(0xffffffffu, mx0, 1));
        mx0 = fmaxf(mx0, __shfl_xor_sync(0xffffffffu, mx0, 2));
        mx1 = fmaxf(mx1, __shfl_xor_sync(0xffffffffu, mx1, 1));
        mx1 = fmaxf(mx1, __shfl_xor_sync(0xffffffffu, mx1, 2));
        const float mn0 = fmaxf(m0, mx0), mn1 = fmaxf(m1, mx1);
        const float c0 = ex2(m0 - mn0), c1 = ex2(m1 - mn1);
        float s0 = 0.f, s1 = 0.f;
#pragma unroll
        for (int nt = 0; nt < 8; nt++) {
            sacc[nt][0] = ex2(sacc[nt][0] - mn0);
            sacc[nt][1] = ex2(sacc[nt][1] - mn0);
            sacc[nt][2] = ex2(sacc[nt][2] - mn1);
            sacc[nt][3] = ex2(sacc[nt][3] - mn1);
            s0 += sacc[nt][0] + sacc[nt][1];
            s1 += sacc[nt][2] + sacc[nt][3];
        }
        s0 += __shfl_xor_sync(0xffffffffu, s0, 1);
        s0 += __shfl_xor_sync(0xffffffffu, s0, 2);
        s1 += __shfl_xor_sync(0xffffffffu, s1, 1);
        s1 += __shfl_xor_sync(0xffffffffu, s1, 2);
        l0 = l0 * c0 + s0;  m0 = mn0;
        l1 = l1 * c1 + s1;  m1 = mn1;
#pragma unroll
        for (int nt = 0; nt < 8; nt++) {
            oacc[nt][0] *= c0; oacc[nt][1] *= c0;
            oacc[nt][2] *= c1; oacc[nt][3] *= c1;
        }

        // P -> smem (warp-private strip), tf32
#pragma unroll
        for (int nt = 0; nt < 8; nt++) {
            uint2 p0 = make_uint2(f2t(sacc[nt][0]), f2t(sacc[nt][1]));
            uint2 p1 = make_uint2(f2t(sacc[nt][2]), f2t(sacc[nt][3]));
            *(uint2*)&SP[(qrow + g)*68 + nt*8 + 2*t]     = p0;
            *(uint2*)&SP[(qrow + 8 + g)*68 + nt*8 + 2*t] = p1;
        }
        __syncwarp();

        // O += P V
#pragma unroll
        for (int kk = 0; kk < 8; kk++) {
            const int k = kk * 8;
            unsigned afr[4];
            const int pb = (qrow + g)*68 + k + t;
            afr[0] = SP[pb];
            afr[1] = SP[pb + 8*68];
            afr[2] = SP[pb + 4];
            afr[3] = SP[pb + 8*68 + 4];
#pragma unroll
            for (int nt = 0; nt < 8; nt++) {
                unsigned b0 = SV[(k + t)*72 + nt*8 + g];
                unsigned b1 = SV[(k + 4 + t)*72 + nt*8 + g];
                mma8(oacc[nt], afr, b0, b1);
            }
        }
        __syncthreads();   // done with SK/SV before next tile load
    }

    // normalize + write merged-head layout [B*S, E]
    const int b = bh >> 4, h = bh & 15;
    const float i0 = 1.0f / l0, i1 = 1.0f / l1;
    const int r0 = q0 + qrow + g;
#pragma unroll
    for (int nt = 0; nt < 8; nt++) {
        const int col = h*64 + nt*8 + 2*t;
        float2 o0, o1;
        o0.x = oacc[nt][0]*i0; o0.y = oacc[nt][1]*i0;
        o1.x = oacc[nt][2]*i1; o1.y = oacc[nt][3]*i1;
        *(float2*)&g_y[((size_t)(b*SEQ + r0))*EMB + col]     = o0;
        *(float2*)&g_y[((size_t)(b*SEQ + r0 + 8))*EMB + col] = o1;
    }
}

// ---------------------------------------------------------------------------
extern "C" void kernel_launch(void* const* d_in, const int* in_sizes, int n_in,
                              void* d_out, int out_size)
{
    const float* x      = (const float*)d_in[0];
    const float* w_qkv  = (const float*)d_in[1];
    const float* b_qkv  = (const float*)d_in[2];
    const float* w_proj = (const float*)d_in[3];
    const float* b_proj = (const float*)d_in[4];
    float* out = (float*)d_out;

    cudaFuncSetAttribute(attn_kernel,
                         cudaFuncAttributeMaxDynamicSharedMemorySize,
                         ATTN_SMEM_BYTES);

    qkv_gemm_kernel<<<dim3(NQKV/128, MTOT/128), 128>>>(x, w_qkv, b_qkv);
    attn_kernel<<<dim3(SEQ/128, BSZ*NH), 256, ATTN_SMEM_BYTES>>>();
    proj_gemm_kernel<<<dim3(EMB/128, MTOT/128), 128>>>(w_proj, b_proj, out);
}

// round 7
// speedup vs baseline: 5.6596x; 1.7909x over previous
#include <cuda_runtime.h>
#include <cuda_fp16.h>
#include <cstdint>

#define BSZ 4
#define SEQ 2048
#define EMB 1024
#define NH  16
#define HD  64
#define MTOT (BSZ*SEQ)       /* 8192 */
#define NQKV (3*EMB)         /* 3072 */
#define NEG_BIG (-3.0e38f)
#define LOG2E 1.4426950408889634f

// Scratch (device globals: allocation-free per harness rules)
__device__ __half g_xh [(size_t)MTOT*EMB];        // x in fp16
__device__ __half g_wh [(size_t)EMB*NQKV];        // w_qkv in fp16
__device__ __half g_wph[(size_t)EMB*EMB];         // w_proj in fp16
__device__ __half g_q[(size_t)BSZ*NH*SEQ*HD];     // [B,H,S,D] fp16
__device__ __half g_k[(size_t)BSZ*NH*SEQ*HD];
__device__ __half g_v[(size_t)BSZ*NH*SEQ*HD];
__device__ __half g_y[(size_t)MTOT*EMB];          // attn out [B*S,E] fp16

// ---------------------------------------------------------------------------
// Helpers
// ---------------------------------------------------------------------------
__device__ __forceinline__ float ex2(float x) {
    float r;
    asm("ex2.approx.ftz.f32 %0, %1;" : "=f"(r) : "f"(x));
    return r;
}
__device__ __forceinline__ uint32_t smem_u32(const void* p) {
    uint32_t a;
    asm("{ .reg .u64 t; cvta.to.shared.u64 t, %1; cvt.u32.u64 %0, t; }"
        : "=r"(a) : "l"(p));
    return a;
}

#define CPA16(dst, src) \
    asm volatile("cp.async.cg.shared.global [%0], [%1], 16;" \
                 :: "r"(dst), "l"(src))
#define CP_COMMIT() asm volatile("cp.async.commit_group;" ::: "memory")
#define CP_WAIT0()  asm volatile("cp.async.wait_group 0;" ::: "memory")

#define LDSM4(r0,r1,r2,r3,addr) \
    asm volatile("ldmatrix.sync.aligned.m8n8.x4.shared.b16 {%0,%1,%2,%3}, [%4];" \
        : "=r"(r0),"=r"(r1),"=r"(r2),"=r"(r3) : "r"(addr))
#define LDSM4T(r0,r1,r2,r3,addr) \
    asm volatile("ldmatrix.sync.aligned.m8n8.x4.trans.shared.b16 {%0,%1,%2,%3}, [%4];" \
        : "=r"(r0),"=r"(r1),"=r"(r2),"=r"(r3) : "r"(addr))

// D += A(16x16) * B(16x8), fp16 in, fp32 accum
__device__ __forceinline__ void mma16(float* c, const uint32_t* a,
                                      uint32_t b0, uint32_t b1) {
    asm volatile(
        "mma.sync.aligned.m16n8k16.row.col.f32.f16.f16.f32 "
        "{%0,%1,%2,%3}, {%4,%5,%6,%7}, {%8,%9}, {%0,%1,%2,%3};"
        : "+f"(c[0]), "+f"(c[1]), "+f"(c[2]), "+f"(c[3])
        : "r"(a[0]), "r"(a[1]), "r"(a[2]), "r"(a[3]), "r"(b0), "r"(b1));
}

// ---------------------------------------------------------------------------
// fp32 -> fp16 convert kernel (8 elems/thread)
// ---------------------------------------------------------------------------
__global__ __launch_bounds__(256) void cvt_kernel(
    const float* __restrict__ src, __half* __restrict__ dst, int n8)
{
    const int i = blockIdx.x * 256 + threadIdx.x;
    if (i >= n8) return;
    const float4* s = (const float4*)src + (size_t)i * 2;
    float4 a = s[0], b = s[1];
    __half2 h[4];
    h[0] = __floats2half2_rn(a.x, a.y);
    h[1] = __floats2half2_rn(a.z, a.w);
    h[2] = __floats2half2_rn(b.x, b.y);
    h[3] = __floats2half2_rn(b.z, b.w);
    *(uint4*)(dst + (size_t)i * 8) = *(uint4*)h;
}

// ---------------------------------------------------------------------------
// fp16 GEMM: CTA 128x128, BK=64, 8 warps (2m x 4n), warp 64x32.
// A smem [128][72] halfs (144B rows), B smem [64][136] halfs (272B rows).
// Both conflict-free for ldmatrix (bank = 4*row mod 32) and 16B STS.
// Double-buffered with cp.async.
// ---------------------------------------------------------------------------
#define GAS 72
#define GBS 136
#define GA_BYTES (128*GAS*2)            /* 18432 */
#define GB_BYTES (64*GBS*2)             /* 17408 */
#define GSTAGE   (GA_BYTES + GB_BYTES)  /* 35840 */
#define GEMM_SMEM (2*GSTAGE)            /* 71680 */
#define GK_ITERS (EMB/64)               /* 16 */

template<int LDW>
__device__ __forceinline__ void g_fill(
    const __half* __restrict__ A, const __half* __restrict__ W,
    int bm, int bn, uint32_t sbase, int kc, int buf)
{
    const int tid = threadIdx.x;
    const uint32_t as = sbase + buf*GSTAGE;
    const uint32_t bs = as + GA_BYTES;
#pragma unroll
    for (int it = 0; it < 4; it++) {          // A: 128 rows x 8 segs
        const int u = it*256 + tid;
        const int r = u >> 3, sg = u & 7;
        CPA16(as + r*144 + sg*16, A + (size_t)(bm + r)*EMB + kc + sg*8);
    }
#pragma unroll
    for (int it = 0; it < 4; it++) {          // B: 64 rows x 16 segs
        const int u = it*256 + tid;
        const int k = u >> 4, sg = u & 15;
        CPA16(bs + k*272 + sg*16, W + (size_t)(kc + k)*LDW + bn + sg*8);
    }
}

__device__ __forceinline__ void g_compute(
    uint32_t sbase, int buf, float acc[4][4][4], int warp, int lane)
{
    const int wm = warp >> 2, wn = warp & 3;
    const uint32_t as = sbase + buf*GSTAGE;
    const uint32_t bs = as + GA_BYTES;
    const int l7 = lane & 7, l8 = (lane >> 3) & 1, l16 = lane >> 4;
#pragma unroll
    for (int ks = 0; ks < 4; ks++) {
        uint32_t a[4][4];
#pragma unroll
        for (int mt = 0; mt < 4; mt++) {
            const int row = wm*64 + mt*16 + l7 + l8*8;
            const int col = ks*16 + l16*8;
            LDSM4(a[mt][0], a[mt][1], a[mt][2], a[mt][3], as + row*144 + col*2);
        }
        uint32_t b[4][2];
#pragma unroll
        for (int np = 0; np < 2; np++) {      // trans: row uses l16, col uses l8
            const int row = ks*16 + l7 + l16*8;
            const int col = wn*32 + np*16 + l8*8;
            uint32_t r0, r1, r2, r3;
            LDSM4T(r0, r1, r2, r3, bs + row*272 + col*2);
            b[np*2  ][0] = r0; b[np*2  ][1] = r2;
            b[np*2+1][0] = r1; b[np*2+1][1] = r3;
        }
#pragma unroll
        for (int mt = 0; mt < 4; mt++)
#pragma unroll
            for (int nt = 0; nt < 4; nt++)
                mma16(acc[mt][nt], a[mt], b[nt][0], b[nt][1]);
    }
}

template<int LDW>
__device__ __forceinline__ void g_mainloop(
    const __half* __restrict__ A, const __half* __restrict__ W,
    int bm, int bn, uint32_t sbase, float acc[4][4][4])
{
    const int warp = threadIdx.x >> 5, lane = threadIdx.x & 31;
#pragma unroll
    for (int mt = 0; mt < 4; mt++)
#pragma unroll
        for (int nt = 0; nt < 4; nt++)
#pragma unroll
            for (int r = 0; r < 4; r++) acc[mt][nt][r] = 0.f;

    g_fill<LDW>(A, W, bm, bn, sbase, 0, 0);
    CP_COMMIT();
    int buf = 0;
    for (int i = 0; i < GK_ITERS; i++) {
        CP_WAIT0();
        __syncthreads();
        if (i + 1 < GK_ITERS) {
            g_fill<LDW>(A, W, bm, bn, sbase, (i+1)*64, buf ^ 1);
            CP_COMMIT();
        }
        g_compute(sbase, buf, acc, warp, lane);
        buf ^= 1;
    }
}

// ---------------------------------------------------------------------------
// QKV GEMM: g_xh[8192,1024] @ g_wh[1024,3072] + b -> g_q/g_k/g_v (fp16)
// ---------------------------------------------------------------------------
__global__ __launch_bounds__(256) void qkv_gemm_kernel(
    const float* __restrict__ bias)
{
    extern __shared__ char smem[];
    const uint32_t sbase = smem_u32(smem);
    const int bm = blockIdx.y * 128, bn = blockIdx.x * 128;

    float acc[4][4][4];
    g_mainloop<NQKV>(g_xh, g_wh, bm, bn, sbase, acc);

    const int warp = threadIdx.x >> 5, lane = threadIdx.x & 31;
    const int wm = warp >> 2, wn = warp & 3;
    const int g = lane >> 2, t4 = lane & 3;
#pragma unroll
    for (int mt = 0; mt < 4; mt++) {
#pragma unroll
        for (int nt = 0; nt < 4; nt++) {
            const int n0 = bn + wn*32 + nt*8 + 2*t4;
            const int sect = n0 >> 10;
            const int e = n0 & (EMB-1);
            const int h = e >> 6, d = e & 63;
            __half* dst = (sect == 0) ? g_q : (sect == 1) ? g_k : g_v;
            const float bx = bias[n0], by = bias[n0+1];
#pragma unroll
            for (int half = 0; half < 2; half++) {
                const int m = bm + wm*64 + mt*16 + g + half*8;
                const int bb = m >> 11, s = m & (SEQ-1);
                __half2 v = __floats2half2_rn(acc[mt][nt][half*2+0] + bx,
                                              acc[mt][nt][half*2+1] + by);
                *(__half2*)&dst[(((size_t)(bb*NH + h))*SEQ + s)*HD + d] = v;
            }
        }
    }
}

// ---------------------------------------------------------------------------
// Proj GEMM: g_y[8192,1024] @ g_wph[1024,1024] + b -> out (fp32)
// ---------------------------------------------------------------------------
__global__ __launch_bounds__(256) void proj_gemm_kernel(
    const float* __restrict__ bias, float* __restrict__ out)
{
    extern __shared__ char smem[];
    const uint32_t sbase = smem_u32(smem);
    const int bm = blockIdx.y * 128, bn = blockIdx.x * 128;

    float acc[4][4][4];
    g_mainloop<EMB>(g_y, g_wph, bm, bn, sbase, acc);

    const int warp = threadIdx.x >> 5, lane = threadIdx.x & 31;
    const int wm = warp >> 2, wn = warp & 3;
    const int g = lane >> 2, t4 = lane & 3;
#pragma unroll
    for (int mt = 0; mt < 4; mt++) {
#pragma unroll
        for (int nt = 0; nt < 4; nt++) {
            const int n0 = bn + wn*32 + nt*8 + 2*t4;
            const float bx = bias[n0], by = bias[n0+1];
#pragma unroll
            for (int half = 0; half < 2; half++) {
                const int m = bm + wm*64 + mt*16 + g + half*8;
                float2 v;
                v.x = acc[mt][nt][half*2+0] + bx;
                v.y = acc[mt][nt][half*2+1] + by;
                *(float2*)&out[(size_t)m*EMB + n0] = v;
            }
        }
    }
}

// ---------------------------------------------------------------------------
// Flash attention, fp16 mma + ldmatrix + cp.async double-buffered KV.
// CTA = 128 q-rows (8 warps x 16), KV tiles of 64.
// smem (halfs): SQ[128][72], SK0/SV0/SK1/SV1 [64][72], SP[128][72]
// ---------------------------------------------------------------------------
#define AQ_OFF  0
#define AK0_OFF 9216
#define AV0_OFF 13824
#define AK1_OFF 18432
#define AV1_OFF 23040
#define ASP_OFF 27648
#define ATTN_SMEM_BYTES (36864*2)       /* 73728 */

__global__ __launch_bounds__(256) void attn_kernel()
{
    extern __shared__ __half smh[];
    const uint32_t su = smem_u32(smh);

    const int tid = threadIdx.x;
    const int w = tid >> 5, lane = tid & 31;
    const int g = lane >> 2, t4 = lane & 3;
    const int l7 = lane & 7, l8 = (lane >> 3) & 1, l16 = lane >> 4;
    const int qt = blockIdx.x, bh = blockIdx.y;
    const int q0 = qt * 128;
    const int qrow = w * 16;
    const size_t base = (size_t)bh * SEQ * HD;
    const __half* Qg = g_q + base;
    const __half* Kg = g_k + base;
    const __half* Vg = g_v + base;

    // Q fill (raw copy, cp.async): 1024 x 16B units
#pragma unroll
    for (int it = 0; it < 4; it++) {
        const int u = it*256 + tid;
        const int r = u >> 3, sg = u & 7;
        CPA16(su + (AQ_OFF + r*72)*2 + sg*16, Qg + (size_t)(q0 + r)*HD + sg*8);
    }
    // KV tile 0 into buf 0
    {
        const uint32_t ak = su + AK0_OFF*2, av = su + AV0_OFF*2;
#pragma unroll
        for (int it = 0; it < 2; it++) {
            const int u = it*256 + tid;
            const int r = u >> 3, sg = u & 7;
            CPA16(ak + r*144 + sg*16, Kg + (size_t)r*HD + sg*8);
            CPA16(av + r*144 + sg*16, Vg + (size_t)r*HD + sg*8);
        }
    }
    CP_COMMIT();

    float m0 = NEG_BIG, m1 = NEG_BIG, l0 = 0.f, l1 = 0.f;
    float oacc[8][4];
#pragma unroll
    for (int nt = 0; nt < 8; nt++)
#pragma unroll
        for (int r = 0; r < 4; r++) oacc[nt][r] = 0.f;

    const float qs2 = 0.125f * LOG2E;
    const int ntiles = 2*qt + 2;
    int buf = 0;
    for (int tk = 0; tk < ntiles; tk++) {
        CP_WAIT0();
        __syncthreads();
        if (tk + 1 < ntiles) {
            const uint32_t ak = su + (buf ? AK0_OFF : AK1_OFF)*2;
            const uint32_t av = su + (buf ? AV0_OFF : AV1_OFF)*2;
#pragma unroll
            for (int it = 0; it < 2; it++) {
                const int u = it*256 + tid;
                const int r = u >> 3, sg = u & 7;
                CPA16(ak + r*144 + sg*16, Kg + (size_t)((tk+1)*64 + r)*HD + sg*8);
                CPA16(av + r*144 + sg*16, Vg + (size_t)((tk+1)*64 + r)*HD + sg*8);
            }
            CP_COMMIT();
        }
        const uint32_t ak = su + (buf ? AK1_OFF : AK0_OFF)*2;
        const uint32_t av = su + (buf ? AV1_OFF : AV0_OFF)*2;

        // S = Q K^T (raw, scale applied in softmax)
        float sacc[8][4];
#pragma unroll
        for (int nt = 0; nt < 8; nt++)
#pragma unroll
            for (int r = 0; r < 4; r++) sacc[nt][r] = 0.f;

#pragma unroll
        for (int ks = 0; ks < 4; ks++) {
            uint32_t a[4];
            {
                const int row = qrow + l7 + l8*8;
                const int col = ks*16 + l16*8;
                LDSM4(a[0], a[1], a[2], a[3], su + (AQ_OFF + row*72 + col)*2);
            }
#pragma unroll
            for (int np = 0; np < 4; np++) {      // kv-tile pairs
                const int row = np*16 + l7 + l8*8;  // kv
                const int col = ks*16 + l16*8;      // d
                uint32_t r0, r1, r2, r3;
                LDSM4(r0, r1, r2, r3, ak + row*144 + col*2);
                mma16(sacc[np*2],   a, r0, r2);
                mma16(sacc[np*2+1], a, r1, r3);
            }
        }

        const int row0 = q0 + qrow + g;
        const int row1 = row0 + 8;
        if (tk >= 2*qt) {    // partially-masked tiles
#pragma unroll
            for (int nt = 0; nt < 8; nt++) {
                const int col = tk*64 + nt*8 + 2*t4;
                if (col   > row0) sacc[nt][0] = NEG_BIG;
                if (col+1 > row0) sacc[nt][1] = NEG_BIG;
                if (col   > row1) sacc[nt][2] = NEG_BIG;
                if (col+1 > row1) sacc[nt][3] = NEG_BIG;
            }
        }

        // online softmax (log2 domain; scale fused into exp arg)
        float mx0 = NEG_BIG, mx1 = NEG_BIG;
#pragma unroll
        for (int nt = 0; nt < 8; nt++) {
            mx0 = fmaxf(mx0, fmaxf(sacc[nt][0], sacc[nt][1]));
            mx1 = fmaxf(mx1, fmaxf(sacc[nt][2], sacc[nt][3]));
        }
        mx0 = fmaxf(mx0, __shfl_xor_sync(0xffffffffu, mx0, 1));
        mx0 = fmaxf(mx0, __shfl_xor_sync(0xffffffffu, mx0, 2));
        mx1 = fmaxf(mx1, __shfl_xor_sync(0xffffffffu, mx1, 1));
        mx1 = fmaxf(mx1, __shfl_xor_sync(0xffffffffu, mx1, 2));
        const float mn0 = fmaxf(m0, mx0 * qs2), mn1 = fmaxf(m1, mx1 * qs2);
        const float c0 = ex2(m0 - mn0), c1 = ex2(m1 - mn1);
        float s0 = 0.f, s1 = 0.f;
        float p[8][4];
#pragma unroll
        for (int nt = 0; nt < 8; nt++) {
            p[nt][0] = ex2(fmaf(sacc[nt][0], qs2, -mn0));
            p[nt][1] = ex2(fmaf(sacc[nt][1], qs2, -mn0));
            p[nt][2] = ex2(fmaf(sacc[nt][2], qs2, -mn1));
            p[nt][3] = ex2(fmaf(sacc[nt][3], qs2, -mn1));
            s0 += p[nt][0] + p[nt][1];
            s1 += p[nt][2] + p[nt][3];
        }
        s0 += __shfl_xor_sync(0xffffffffu, s0, 1);
        s0 += __shfl_xor_sync(0xffffffffu, s0, 2);
        s1 += __shfl_xor_sync(0xffffffffu, s1, 1);
        s1 += __shfl_xor_sync(0xffffffffu, s1, 2);
        l0 = l0 * c0 + s0;  m0 = mn0;
        l1 = l1 * c1 + s1;  m1 = mn1;
#pragma unroll
        for (int nt = 0; nt < 8; nt++) {
            oacc[nt][0] *= c0; oacc[nt][1] *= c0;
            oacc[nt][2] *= c1; oacc[nt][3] *= c1;
        }

        // P -> smem (warp-private strip), fp16
#pragma unroll
        for (int nt = 0; nt < 8; nt++) {
            *(__half2*)&smh[ASP_OFF + (qrow + g)*72 + nt*8 + 2*t4] =
                __floats2half2_rn(p[nt][0], p[nt][1]);
            *(__half2*)&smh[ASP_OFF + (qrow + 8 + g)*72 + nt*8 + 2*t4] =
                __floats2half2_rn(p[nt][2], p[nt][3]);
        }
        __syncwarp();

        // O += P V
#pragma unroll
        for (int kk = 0; kk < 4; kk++) {
            uint32_t a[4];
            {
                const int row = qrow + l7 + l8*8;
                const int col = kk*16 + l16*8;
                LDSM4(a[0], a[1], a[2], a[3], su + (ASP_OFF + row*72 + col)*2);
            }
#pragma unroll
            for (int dp = 0; dp < 4; dp++) {       // d-tile pairs (trans)
                const int row = kk*16 + l7 + l16*8;  // kv
                const int col = dp*16 + l8*8;        // d
                uint32_t r0, r1, r2, r3;
                LDSM4T(r0, r1, r2, r3, av + row*144 + col*2);
                mma16(oacc[dp*2],   a, r0, r2);
                mma16(oacc[dp*2+1], a, r1, r3);
            }
        }
        buf ^= 1;
    }

    // normalize + write merged-head layout [B*S, E] fp16
    const int b = bh >> 4, h = bh & 15;
    const float i0 = 1.0f / l0, i1 = 1.0f / l1;
    const int r0 = q0 + qrow + g;
#pragma unroll
    for (int nt = 0; nt < 8; nt++) {
        const int col = h*64 + nt*8 + 2*t4;
        *(__half2*)&g_y[((size_t)(b*SEQ + r0))*EMB + col] =
            __floats2half2_rn(oacc[nt][0]*i0, oacc[nt][1]*i0);
        *(__half2*)&g_y[((size_t)(b*SEQ + r0 + 8))*EMB + col] =
            __floats2half2_rn(oacc[nt][2]*i1, oacc[nt][3]*i1);
    }
}

// ---------------------------------------------------------------------------
extern "C" void kernel_launch(void* const* d_in, const int* in_sizes, int n_in,
                              void* d_out, int out_size)
{
    const float* x      = (const float*)d_in[0];
    const float* w_qkv  = (const float*)d_in[1];
    const float* b_qkv  = (const float*)d_in[2];
    const float* w_proj = (const float*)d_in[3];
    const float* b_proj = (const float*)d_in[4];
    float* out = (float*)d_out;

    cudaFuncSetAttribute(qkv_gemm_kernel,
                         cudaFuncAttributeMaxDynamicSharedMemorySize, GEMM_SMEM);
    cudaFuncSetAttribute(proj_gemm_kernel,
                         cudaFuncAttributeMaxDynamicSharedMemorySize, GEMM_SMEM);
    cudaFuncSetAttribute(attn_kernel,
                         cudaFuncAttributeMaxDynamicSharedMemorySize, ATTN_SMEM_BYTES);

    __half* xh;  cudaGetSymbolAddress((void**)&xh,  g_xh);
    __half* wh;  cudaGetSymbolAddress((void**)&wh,  g_wh);
    __half* wph; cudaGetSymbolAddress((void**)&wph, g_wph);

    cvt_kernel<<<(MTOT*EMB/8 + 255)/256, 256>>>(x, xh, MTOT*EMB/8);
    cvt_kernel<<<(EMB*NQKV/8 + 255)/256, 256>>>(w_qkv, wh, EMB*NQKV/8);
    cvt_kernel<<<(EMB*EMB/8 + 255)/256, 256>>>(w_proj, wph, EMB*EMB/8);

    qkv_gemm_kernel<<<dim3(NQKV/128, MTOT/128), 256, GEMM_SMEM>>>(b_qkv);
    attn_kernel<<<dim3(SEQ/128, BSZ*NH), 256, ATTN_SMEM_BYTES>>>();
    proj_gemm_kernel<<<dim3(EMB/128, MTOT/128), 256, GEMM_SMEM>>>(b_proj, out);
}